// round 9
// baseline (speedup 1.0000x reference)
#include <cuda_runtime.h>

typedef unsigned long long ull;

// 201 MB ping-pong scratch (allocation-free rule: __device__ global)
__device__ float g_buf[16u * 3u * 1024u * 1024u];
// pre-packed (w,w) f32x2 weights, layout [ci][kx][s=co*5+ky] padded to 16
__device__ ull   g_wpack[240];

__device__ __forceinline__ ull pack2(float lo, float hi) {
    ull r;
    asm("mov.b64 %0, {%1, %2};" : "=l"(r) : "f"(lo), "f"(hi));
    return r;
}
__device__ __forceinline__ float2 unpack2(ull v) {
    float2 r;
    asm("mov.b64 {%0, %1}, %2;" : "=f"(r.x), "=f"(r.y) : "l"(v));
    return r;
}
// packed fp32x2 FMA (FFMA2) -- only reachable via PTX fma.rn.f32x2
__device__ __forceinline__ void fma2(ull& d, ull a, ull b) {
    asm("fma.rn.f32x2 %0, %1, %2, %0;" : "+l"(d) : "l"(a), "l"(b));
}

// prep: broadcast-pack weights once; W is OIHW [co][ci][ky][kx] = [3][3][5][5]
__global__ void pack_w(const float* __restrict__ W) {
    int i = threadIdx.x;
    if (i >= 240) return;
    int ci = i / 80;
    int r  = i - ci * 80;
    int kx = r / 16;
    int s  = r - kx * 16;
    float w = 0.0f;
    if (s < 15) {
        int co = s / 5;
        int ky = s - co * 5;
        w = W[co * 75 + ci * 25 + ky * 5 + kx];
    }
    g_wpack[i] = pack2(w, w);
}

// 8 packed FMAs: one weight pair against window rows base..base+7
__device__ __forceinline__ void fma8(ull* accrow, const ull* base, ull w) {
    #pragma unroll
    for (int p = 0; p < 8; ++p)
        fma2(accrow[p], base[p], w);
}
// 12 conflict-free LDS.64: one column window, all pair-rows
__device__ __forceinline__ void load_window(ull* rv, const float2* colbase, int kx) {
    #pragma unroll
    for (int p = 0; p < 12; ++p)
        rv[p] = *reinterpret_cast<const ull*>(colbase + p * 132 + kx);
}
// one (ci,kx) chunk: 8 weight LDS.128 pairs + 120 FFMA2 (R5/R6-proven order)
__device__ __forceinline__ void fchunk(ull (*acc)[8], const ull* rv, const ull* wrow) {
    const ulonglong2* wv = reinterpret_cast<const ulonglong2*>(wrow);
    #pragma unroll
    for (int j = 0; j < 7; ++j) {
        ulonglong2 q = wv[j];
        const int s0 = 2 * j;
        const int s1 = 2 * j + 1;
        fma8(acc[s0 / 5], rv + (s0 % 5), q.x);
        fma8(acc[s1 / 5], rv + (s1 % 5), q.y);
    }
    fma8(acc[2], rv + 4, wrow[14]);   // s=14 -> co=2, ky=4
}

// SMEM (dynamic): smx float2[3][20][132] (63360 B) + wS ull[240] (1920 B)
#define SMX_BYTES 63360
#define DSMEM_BYTES (SMX_BYTES + 1920)

// Block: 256 threads (tx=tid&127 column, ty=tid>>7 row-half).
// Tile: 128 cols x 32 rows x 3 ch.  Pairing (r, r+16):
//   smx[ch][q][xi] = (row rb+q-2, row rb+q+14), xi-2 = col offset.
// ty=0 computes output pairs rows (rb+p, rb+p+16), window q = p..p+4  (q 0..11)
// ty=1 computes rows (rb+8+p, rb+24+p),          window q = 8+p..12+p (q 8..19)
// Hot loop identical to R6; only the window base offset differs by 8*ty rows.
__global__ void __launch_bounds__(256, 2) ca_step(const float* __restrict__ src,
                                                  float* __restrict__ dst)
{
    extern __shared__ __align__(16) char dsm[];
    float2 (*smx)[20][132] = reinterpret_cast<float2(*)[20][132]>(dsm);
    ull*    wS             = reinterpret_cast<ull*>(dsm + SMX_BYTES);

    const int tid = threadIdx.x;
    const int tx  = tid & 127;
    const int ty  = tid >> 7;
    const int xb  = blockIdx.x * 128;
    const int rb  = blockIdx.y * 32;
    const int img = blockIdx.z;

    // ---- weights -> smem ----
    if (tid < 120) {
        wS[tid]       = g_wpack[tid];
        wS[tid + 120] = g_wpack[tid + 120];
    }

    // ---- interior tile load: 3ch x 20 pair-rows x 32 float4-groups = 1920 items ----
    #pragma unroll 1
    for (int k = 0; k < 8; ++k) {
        int i = tid + k * 256;
        if (i < 1920) {
            int ch  = i / 640;
            int rem = i - ch * 640;
            int q   = rem >> 5;
            int g   = rem & 31;
            int rA  = (rb + q - 2)  & 1023;
            int rB  = (rb + q + 14) & 1023;
            const float* cbase = src + (((size_t)(img * 3 + ch)) << 20) + xb + g * 4;
            float4 a = *reinterpret_cast<const float4*>(cbase + (rA << 10));
            float4 b = *reinterpret_cast<const float4*>(cbase + (rB << 10));
            float4* s = reinterpret_cast<float4*>(&smx[ch][q][2 + g * 4]);
            s[0] = make_float4(a.x, b.x, a.y, b.y);
            s[1] = make_float4(a.z, b.z, a.w, b.w);
        }
    }
    // ---- halo columns (wrap): 3ch x 20q x 4 = 240 items, one trip ----
    if (tid < 240) {
        int ch  = tid / 80;
        int rem = tid - ch * 80;
        int q   = rem >> 2;
        int j   = rem & 3;
        int xi  = (j < 2) ? j : (j + 128);
        int col = (xb + xi - 2) & 1023;
        int rA  = (rb + q - 2)  & 1023;
        int rB  = (rb + q + 14) & 1023;
        const float* base = src + (((size_t)(img * 3 + ch)) << 20);
        smx[ch][q][xi] = make_float2(__ldg(base + (rA << 10) + col),
                                     __ldg(base + (rB << 10) + col));
    }
    __syncthreads();

    // ---- conv accumulation: 3 out-channels x 8 pair-rows, packed f32x2 ----
    ull acc[3][8];
    #pragma unroll
    for (int co = 0; co < 3; ++co)
        #pragma unroll
        for (int p = 0; p < 8; ++p)
            acc[co][p] = 0ull;

    const int qoff = ty * 8;
    const float2* cb0 = &smx[0][qoff][tx];
    const float2* cb1 = &smx[1][qoff][tx];
    const float2* cb2 = &smx[2][qoff][tx];

    ull rvA[12], rvB[12];
    // 15 chunks (ci,kx), 2-deep pipeline (R6-proven)
    load_window(rvA, cb0, 0);
    load_window(rvB, cb0, 1);  fchunk(acc, rvA, &wS[0 * 80 + 0 * 16]);
    load_window(rvA, cb0, 2);  fchunk(acc, rvB, &wS[0 * 80 + 1 * 16]);
    load_window(rvB, cb0, 3);  fchunk(acc, rvA, &wS[0 * 80 + 2 * 16]);
    load_window(rvA, cb0, 4);  fchunk(acc, rvB, &wS[0 * 80 + 3 * 16]);
    load_window(rvB, cb1, 0);  fchunk(acc, rvA, &wS[0 * 80 + 4 * 16]);
    load_window(rvA, cb1, 1);  fchunk(acc, rvB, &wS[1 * 80 + 0 * 16]);
    load_window(rvB, cb1, 2);  fchunk(acc, rvA, &wS[1 * 80 + 1 * 16]);
    load_window(rvA, cb1, 3);  fchunk(acc, rvB, &wS[1 * 80 + 2 * 16]);
    load_window(rvB, cb1, 4);  fchunk(acc, rvA, &wS[1 * 80 + 3 * 16]);
    load_window(rvA, cb2, 0);  fchunk(acc, rvB, &wS[1 * 80 + 4 * 16]);
    load_window(rvB, cb2, 1);  fchunk(acc, rvA, &wS[2 * 80 + 0 * 16]);
    load_window(rvA, cb2, 2);  fchunk(acc, rvB, &wS[2 * 80 + 1 * 16]);
    load_window(rvB, cb2, 3);  fchunk(acc, rvA, &wS[2 * 80 + 2 * 16]);
    load_window(rvA, cb2, 4);  fchunk(acc, rvB, &wS[2 * 80 + 3 * 16]);
                               fchunk(acc, rvA, &wS[2 * 80 + 4 * 16]);

    // ---- epilogue: out = clip(x + 0.1*relu(y), 0, 1) ----
    const int col = xb + tx;
    const int r0  = rb + qoff;           // thread's first output row
    #pragma unroll
    for (int co = 0; co < 3; ++co) {
        float* ob = dst + (((size_t)(img * 3 + co)) << 20) + col;
        #pragma unroll
        for (int p = 0; p < 8; ++p) {
            float2 y  = unpack2(acc[co][p]);
            float2 xp = smx[co][qoff + p + 2][tx + 2];   // pair (r0+p, r0+p+16)
            ob[(r0 + p)      << 10] = __saturatef(fmaf(fmaxf(y.x, 0.0f), 0.1f, xp.x));
            ob[(r0 + p + 16) << 10] = __saturatef(fmaf(fmaxf(y.y, 0.0f), 0.1f, xp.y));
        }
    }
}

extern "C" void kernel_launch(void* const* d_in, const int* in_sizes, int n_in,
                              void* d_out, int out_size)
{
    const float* x = (const float*)d_in[0];
    const float* W = (const float*)d_in[1];
    float* out = (float*)d_out;

    float* scratch = nullptr;
    cudaGetSymbolAddress((void**)&scratch, g_buf);

    cudaFuncSetAttribute(ca_step, cudaFuncAttributeMaxDynamicSharedMemorySize,
                         DSMEM_BYTES);

    pack_w<<<1, 256>>>(W);

    dim3 grid(8, 32, 16);   // 1024/128 cols, 1024/32 rows, 16 images
    dim3 block(256);

    const float* src = x;
    for (int s = 0; s < 10; ++s) {
        float* dst = (s & 1) ? out : scratch;  // step 9 (last) lands in d_out
        ca_step<<<grid, block, DSMEM_BYTES>>>(src, dst);
        src = dst;
    }
}